// round 16
// baseline (speedup 1.0000x reference)
#include <cuda_runtime.h>
#include <cuda_fp16.h>
#include <math.h>
#include <stdint.h>

// Problem constants
#define BQ   2
#define SEQ  2048
#define DIM  1024
#define NH   16
#define HDIM 64
#define MROWS (BQ * SEQ)   // 4096
#define LOG2E 1.4426950408889634f
#define SPLIT_MIN 20       // split CTAs with >= this many 64-key tiles

// Scratch: everything single fp16 (calibrated error budget allows it).
__device__ __half gXh[MROWS * DIM];
__device__ __half gWh[4 * DIM * DIM];
__device__ __half gQh[MROWS * DIM];
__device__ __half gKh[MROWS * DIM];
__device__ __half gVh[MROWS * DIM];
__device__ __half gOh[MROWS * DIM];
// split-KV partials (unnormalized O + per-row max/sum in log2 domain)
__device__ float gOp[2][(size_t)MROWS * DIM];
__device__ float gMp[2][MROWS * NH];
__device__ float gLp[2][MROWS * NH];

// ---------------------------------------------------------------------------
// Helpers
// ---------------------------------------------------------------------------
__device__ __forceinline__ uint32_t smem_u32(const void* p) {
    uint32_t a;
    asm("{ .reg .u64 t; cvta.to.shared.u64 t, %1; cvt.u32.u64 %0, t; }"
        : "=r"(a) : "l"(p));
    return a;
}
__device__ __forceinline__ void cp16(uint32_t dst, const void* src) {
    asm volatile("cp.async.cg.shared.global [%0], [%1], 16;"
                 :: "r"(dst), "l"(__cvta_generic_to_global(src)));
}
__device__ __forceinline__ void cp_commit() {
    asm volatile("cp.async.commit_group;" ::: "memory");
}
__device__ __forceinline__ void ldsm4(uint32_t* r, uint32_t addr) {
    asm volatile("ldmatrix.sync.aligned.m8n8.x4.shared.b16 {%0,%1,%2,%3}, [%4];"
                 : "=r"(r[0]), "=r"(r[1]), "=r"(r[2]), "=r"(r[3]) : "r"(addr));
}
__device__ __forceinline__ void ldsm4t(uint32_t* r, uint32_t addr) {
    asm volatile("ldmatrix.sync.aligned.m8n8.x4.trans.shared.b16 {%0,%1,%2,%3}, [%4];"
                 : "=r"(r[0]), "=r"(r[1]), "=r"(r[2]), "=r"(r[3]) : "r"(addr));
}
__device__ __forceinline__ void mma16816(float* c, const uint32_t* a, const uint32_t* b) {
    asm volatile(
        "mma.sync.aligned.m16n8k16.row.col.f32.f16.f16.f32 "
        "{%0,%1,%2,%3}, {%4,%5,%6,%7}, {%8,%9}, {%0,%1,%2,%3};"
        : "+f"(c[0]), "+f"(c[1]), "+f"(c[2]), "+f"(c[3])
        : "r"(a[0]), "r"(a[1]), "r"(a[2]), "r"(a[3]), "r"(b[0]), "r"(b[1]));
}
__device__ __forceinline__ uint32_t pack_f2h(float a, float b) {
    __half2 t = __halves2half2(__float2half_rn(a), __float2half_rn(b));
    return *(uint32_t*)&t;
}

// ---------------------------------------------------------------------------
// Convert fp32 inputs -> single fp16 (X and the 4 weight matrices)
// ---------------------------------------------------------------------------
__global__ __launch_bounds__(256) void convert_inputs(
    const float* __restrict__ X, const float* __restrict__ Wq,
    const float* __restrict__ Wk, const float* __restrict__ Wv,
    const float* __restrict__ Wo) {
    const int XQ = MROWS * DIM / 4;
    const int WQ = DIM * DIM / 4;
    const int total4 = XQ + 4 * WQ;
    for (int i = blockIdx.x * blockDim.x + threadIdx.x; i < total4;
         i += gridDim.x * blockDim.x) {
        const float* src;
        __half* dh;
        if (i < XQ) {
            int e = i * 4;
            src = X + e; dh = gXh + e;
        } else {
            int t = i - XQ;
            int w = t / WQ;
            int off = (t - w * WQ) * 4;
            src = (w == 0) ? Wq + off : (w == 1) ? Wk + off
                  : (w == 2) ? Wv + off : Wo + off;
            dh = gWh + (size_t)w * DIM * DIM + off;
        }
        float4 v = *(const float4*)src;
        ((uint32_t*)dh)[0] = pack_f2h(v.x, v.y);
        ((uint32_t*)dh)[1] = pack_f2h(v.z, v.w);
    }
}

// ---------------------------------------------------------------------------
// Single-term fp16 GEMM (R15 config, unchanged): 128x128 CTA tile, K-step 64,
// 8 warps (64x32 tiles), 2-stage cp.async, 2 CTAs/SM.
// ---------------------------------------------------------------------------
#define STAGE_BYTES 32768
#define SM_BH 16384
#define GEMM_SMEM (2 * STAGE_BYTES)

__device__ __forceinline__ void gemm_fill(uint32_t sbuf,
                                          const __half* __restrict__ A,
                                          const __half* __restrict__ B,
                                          int row0, int col0, int kt, int tid) {
#pragma unroll
    for (int i = 0; i < 4; ++i) {
        int lin = tid + i * 256;
        int m = lin >> 3, c = lin & 7;
        cp16(sbuf + m * 128 + ((c ^ (m & 7)) << 4),
             A + (size_t)(row0 + m) * DIM + kt + c * 8);
    }
#pragma unroll
    for (int i = 0; i < 4; ++i) {
        int lin = tid + i * 256;
        int k = lin >> 4, c = lin & 15;
        cp16(sbuf + SM_BH + k * 256 + ((c >> 3) << 7) +
                 (((c & 7) ^ (k & 7)) << 4),
             B + (size_t)(kt + k) * DIM + col0 + c * 8);
    }
}

template <int OMODE>
__device__ __forceinline__ void mma_gemm_body(
    const __half* __restrict__ Ag, const __half* __restrict__ Bg,
    const float* __restrict__ bias, float* __restrict__ Yf,
    __half* __restrict__ Yh) {
    extern __shared__ __align__(1024) char smem[];
    const uint32_t sb = smem_u32(smem);
    const int tid = threadIdx.x;
    const int row0 = blockIdx.y * 128, col0 = blockIdx.x * 128;
    const int lane = tid & 31, wid = tid >> 5;
    const int wm = wid & 1, wn = wid >> 1;
    const int q = lane >> 3, r = lane & 7;
    const int arow = (q & 1) * 8 + r;
    const int aq = q >> 1;

    float acc[4][4][4];
#pragma unroll
    for (int mt = 0; mt < 4; ++mt)
#pragma unroll
        for (int nt = 0; nt < 4; ++nt)
#pragma unroll
            for (int e = 0; e < 4; ++e) acc[mt][nt][e] = 0.f;

    gemm_fill(sb, Ag, Bg, row0, col0, 0, tid);
    cp_commit();

    for (int s = 0; s < 16; ++s) {
        const int buf = s & 1;
        if (s + 1 < 16) {
            gemm_fill(sb + (buf ^ 1) * STAGE_BYTES, Ag, Bg, row0, col0,
                      (s + 1) * 64, tid);
            cp_commit();
            asm volatile("cp.async.wait_group 1;" ::: "memory");
        } else {
            asm volatile("cp.async.wait_group 0;" ::: "memory");
        }
        __syncthreads();

        const uint32_t sA = sb + buf * STAGE_BYTES;
        const uint32_t sBh = sA + SM_BH;

#pragma unroll
        for (int k16 = 0; k16 < 4; ++k16) {
            uint32_t bh[8];
            {
                const int krow = k16 * 16 + (q & 1) * 8 + r;
#pragma unroll
                for (int g2 = 0; g2 < 2; ++g2) {
                    int cg = wn * 4 + g2 * 2 + (q >> 1);
                    uint32_t baddr = krow * 256 + ((cg >> 3) << 7) +
                                     (((cg & 7) ^ (krow & 7)) << 4);
                    ldsm4t(&bh[g2 * 4], sBh + baddr);
                }
            }
            uint32_t ah[4][4];
#pragma unroll
            for (int mt = 0; mt < 4; ++mt) {
                int row = wm * 64 + mt * 16 + arow;
                int c1 = k16 * 2 + aq;
                ldsm4(ah[mt], sA + row * 128 + ((c1 ^ r) << 4));
            }
#pragma unroll
            for (int mt = 0; mt < 4; ++mt)
#pragma unroll
                for (int nt = 0; nt < 4; ++nt)
                    mma16816(acc[mt][nt], ah[mt], &bh[(nt >> 1) * 4 + (nt & 1) * 2]);
        }
        __syncthreads();
    }

    const int cg = lane >> 2, ct = lane & 3;
#pragma unroll
    for (int mt = 0; mt < 4; ++mt) {
        int r0 = row0 + wm * 64 + mt * 16 + cg;
#pragma unroll
        for (int nt = 0; nt < 4; ++nt) {
            int col = col0 + wn * 32 + nt * 8 + ct * 2;
            float b0 = bias ? bias[col] : 0.f;
            float b1 = bias ? bias[col + 1] : 0.f;
            float v00 = acc[mt][nt][0] + b0, v01 = acc[mt][nt][1] + b1;
            float v10 = acc[mt][nt][2] + b0, v11 = acc[mt][nt][3] + b1;
            if (OMODE == 0) {
                *(float2*)(Yf + (size_t)r0 * DIM + col) = make_float2(v00, v01);
                *(float2*)(Yf + (size_t)(r0 + 8) * DIM + col) = make_float2(v10, v11);
            } else {
                *(uint32_t*)&Yh[(size_t)r0 * DIM + col] = pack_f2h(v00, v01);
                *(uint32_t*)&Yh[(size_t)(r0 + 8) * DIM + col] = pack_f2h(v10, v11);
            }
        }
    }
}

__global__ __launch_bounds__(256, 2) void qkv_mma(const float* __restrict__ bq,
                                                  const float* __restrict__ bk) {
    const int z = blockIdx.z;
    const __half* B = gWh + (size_t)z * DIM * DIM;
    const float* bias = (z == 0) ? bq : (z == 1) ? bk : nullptr;
    __half* Yh = (z == 0) ? gQh : (z == 1) ? gKh : gVh;
    mma_gemm_body<3>(gXh, B, bias, nullptr, Yh);
}

__global__ __launch_bounds__(256, 2) void out_mma(const float* __restrict__ bo,
                                                  float* __restrict__ out) {
    mma_gemm_body<0>(gOh, gWh + (size_t)3 * DIM * DIM, bo, out, nullptr);
}

// ---------------------------------------------------------------------------
// Flash attention with split-KV for heavy CTAs. j-tile = 64, 3-stage pipeline,
// 2 CTAs/SM. Log2-domain softmax (R15). CTAs whose ALiBi/causal window has
// >= SPLIT_MIN tiles are split along j into two CTAs (z); each emits an
// unnormalized partial (O fp32, m, l) merged by attn_combine.
// grid = (32, 32): blockIdx.x encodes (it, z) interleaved so both halves of
// heavy CTAs schedule in wave 1.
// ---------------------------------------------------------------------------
#define A_ST0 16384
#define A_STAGE 16384
#define ATTN_SMEM (16384 + 3 * 16384)

__device__ __forceinline__ void attn_fill_kv(uint32_t st, int krow_base,
                                             int hcol, int tid) {
#pragma unroll
    for (int i = 0; i < 4; ++i) {
        int lin = tid + i * 256;
        int tz = lin >> 9;            // 0=Kh 1=Vh
        int rem = lin & 511;
        int m = rem >> 3, c = rem & 7;
        const __half* src = (tz ? gVh : gKh) +
                            (size_t)(krow_base + m) * DIM + hcol + c * 8;
        cp16(st + tz * 8192 + m * 128 + ((c ^ (m & 7)) << 4), src);
    }
}

__global__ __launch_bounds__(256, 2) void attn_mma() {
    extern __shared__ __align__(1024) char smem[];
    const uint32_t sb = smem_u32(smem);
    const int tid = threadIdx.x;
    const int lane = tid & 31, w = tid >> 5;
    const int q = lane >> 3, r = lane & 7;
    const int g = lane >> 2, t = lane & 3;
    const int itz = blockIdx.x;
    const int it = 15 - (itz >> 1);          // heavy i-tiles first
    const int z = itz & 1;
    const int y = blockIdx.y;
    const int b = y & 1;
    const int h = 15 - (y >> 1);             // heavy heads first
    const int i0 = it * 128;
    const float slope = exp2f(-0.5f * (float)(h + 1));
    const float qsc = 0.125f * LOG2E;
    const float sl2 = slope * LOG2E;
    const int qrow_base = b * SEQ + i0;
    const int hcol = h * HDIM;
    const int kbase = b * SEQ;

    // window (bit-exact) + split decision
    const int Jt_cap = min(32, (int)(100.f / slope) / 64 + 1);
    const int JtF = min(2 * it + 2, Jt_cap);        // >= 2
    const bool split = (JtF >= SPLIT_MIN);
    if (!split && z) return;
    const int jlo = (split && z) ? (JtF >> 1) : 0;
    const int jhi = split ? (z ? JtF : (JtF >> 1)) : JtF;   // span >= 2 always

    // ---- fill Q (16KB) + K/V stages jlo, jlo+1 ----
#pragma unroll
    for (int i = 0; i < 4; ++i) {
        int lin = tid + i * 256;
        int m = lin >> 3, c = lin & 7;
        cp16(sb + m * 128 + ((c ^ (m & 7)) << 4),
             gQh + (size_t)(qrow_base + m) * DIM + hcol + c * 8);
    }
    attn_fill_kv(sb + A_ST0, kbase + jlo * 64, hcol, tid);
    cp_commit();
    attn_fill_kv(sb + A_ST0 + A_STAGE, kbase + (jlo + 1) * 64, hcol, tid);
    cp_commit();

    float o[8][4];
#pragma unroll
    for (int nt = 0; nt < 8; ++nt)
#pragma unroll
        for (int e = 0; e < 4; ++e) o[nt][e] = 0.f;
    float m0 = -1e30f, m1 = -1e30f, l0 = 0.f, l1 = 0.f;
    uint32_t qh[4][4];

    const int rowlast = i0 + w * 16 + 15;
    for (int jt = jlo; jt < jhi; ++jt) {
        const int buf = (jt - jlo) % 3;
        if (jt + 2 < jhi) {
            attn_fill_kv(sb + A_ST0 + ((jt - jlo + 2) % 3) * A_STAGE,
                         kbase + (jt + 2) * 64, hcol, tid);
            cp_commit();
            asm volatile("cp.async.wait_group 2;" ::: "memory");
        } else if (jt + 1 < jhi) {
            asm volatile("cp.async.wait_group 1;" ::: "memory");
        } else {
            asm volatile("cp.async.wait_group 0;" ::: "memory");
        }
        __syncthreads();

        if (jt == jlo) {  // hoist Q fragments
#pragma unroll
            for (int k16 = 0; k16 < 4; ++k16) {
                int row = w * 16 + (q & 1) * 8 + r;
                int c = k16 * 2 + (q >> 1);
                ldsm4(qh[k16], sb + row * 128 + ((c ^ r) << 4));
            }
        }

        const uint32_t sk = sb + A_ST0 + buf * A_STAGE;
        const uint32_t sv = sk + 8192;
        const int j0 = jt * 64;
        const bool maskzone = (j0 + 63) > (i0 + w * 16);

        // ---- S = Q K^T over 64 keys ----
        float s[8][4];
#pragma unroll
        for (int nt16 = 0; nt16 < 4; ++nt16) {
#pragma unroll
            for (int e = 0; e < 4; ++e) {
                s[2 * nt16][e] = 0.f;
                s[2 * nt16 + 1][e] = 0.f;
            }
            if (j0 + nt16 * 16 > rowlast) continue;
            const int row = nt16 * 16 + (q >> 1) * 8 + r;
#pragma unroll
            for (int k16 = 0; k16 < 4; ++k16) {
                const int c = k16 * 2 + (q & 1);
                uint32_t kh[4];
                ldsm4(kh, sk + row * 128 + ((c ^ r) << 4));
                mma16816(s[2 * nt16], qh[k16], kh);
                mma16816(s[2 * nt16 + 1], qh[k16], kh + 2);
            }
        }

        // ---- online softmax (log2 domain) ----
        const int rowg0 = i0 + w * 16 + g;
        const int rowg1 = rowg0 + 8;
        float mx0 = -1e30f, mx1 = -1e30f;
#pragma unroll
        for (int nt = 0; nt < 8; ++nt) {
            const int jc = j0 + nt * 8 + 2 * t;
            const float c0 = (float)jc;
            s[nt][0] = s[nt][0] * qsc - sl2 * c0;
            s[nt][1] = s[nt][1] * qsc - sl2 * (c0 + 1.f);
            s[nt][2] = s[nt][2] * qsc - sl2 * c0;
            s[nt][3] = s[nt][3] * qsc - sl2 * (c0 + 1.f);
            if (maskzone) {
                if (jc > rowg0) s[nt][0] = -1e30f;
                if (jc + 1 > rowg0) s[nt][1] = -1e30f;
                if (jc > rowg1) s[nt][2] = -1e30f;
                if (jc + 1 > rowg1) s[nt][3] = -1e30f;
            }
            mx0 = fmaxf(mx0, fmaxf(s[nt][0], s[nt][1]));
            mx1 = fmaxf(mx1, fmaxf(s[nt][2], s[nt][3]));
        }
        mx0 = fmaxf(mx0, __shfl_xor_sync(0xffffffffu, mx0, 1, 4));
        mx0 = fmaxf(mx0, __shfl_xor_sync(0xffffffffu, mx0, 2, 4));
        mx1 = fmaxf(mx1, __shfl_xor_sync(0xffffffffu, mx1, 1, 4));
        mx1 = fmaxf(mx1, __shfl_xor_sync(0xffffffffu, mx1, 2, 4));
        const float mn0 = fmaxf(m0, mx0), mn1 = fmaxf(m1, mx1);
        const float cr0 = exp2f(m0 - mn0), cr1 = exp2f(m1 - mn1);
        m0 = mn0;
        m1 = mn1;
        float sum0 = 0.f, sum1 = 0.f;
#pragma unroll
        for (int nt = 0; nt < 8; ++nt) {
            s[nt][0] = exp2f(s[nt][0] - mn0);
            s[nt][1] = exp2f(s[nt][1] - mn0);
            s[nt][2] = exp2f(s[nt][2] - mn1);
            s[nt][3] = exp2f(s[nt][3] - mn1);
            sum0 += s[nt][0] + s[nt][1];
            sum1 += s[nt][2] + s[nt][3];
        }
        sum0 += __shfl_xor_sync(0xffffffffu, sum0, 1, 4);
        sum0 += __shfl_xor_sync(0xffffffffu, sum0, 2, 4);
        sum1 += __shfl_xor_sync(0xffffffffu, sum1, 1, 4);
        sum1 += __shfl_xor_sync(0xffffffffu, sum1, 2, 4);
        l0 = l0 * cr0 + sum0;
        l1 = l1 * cr1 + sum1;
#pragma unroll
        for (int nt = 0; nt < 8; ++nt) {
            o[nt][0] *= cr0;
            o[nt][1] *= cr0;
            o[nt][2] *= cr1;
            o[nt][3] *= cr1;
        }

        // ---- O += P V over 64 keys ----
#pragma unroll
        for (int k16 = 0; k16 < 4; ++k16) {
            if (j0 + k16 * 16 > rowlast) continue;
            uint32_t ph[4];
            ph[0] = pack_f2h(s[2 * k16][0], s[2 * k16][1]);
            ph[1] = pack_f2h(s[2 * k16][2], s[2 * k16][3]);
            ph[2] = pack_f2h(s[2 * k16 + 1][0], s[2 * k16 + 1][1]);
            ph[3] = pack_f2h(s[2 * k16 + 1][2], s[2 * k16 + 1][3]);
            const int row = k16 * 16 + (q & 1) * 8 + r;
#pragma unroll
            for (int cgp = 0; cgp < 4; ++cgp) {
                const int c = cgp * 2 + (q >> 1);
                uint32_t vh[4];
                ldsm4t(vh, sv + row * 128 + ((c ^ r) << 4));
                mma16816(o[cgp * 2], ph, vh);
                mma16816(o[cgp * 2 + 1], ph, vh + 2);
            }
        }
        __syncthreads();
    }

    // ---- epilogue ----
    const int rg0 = qrow_base + w * 16 + g;
    const size_t orow0 = (size_t)rg0 * DIM + hcol;
    const size_t orow1 = orow0 + (size_t)8 * DIM;
    if (!split) {
        const float inv0 = 1.f / l0, inv1 = 1.f / l1;
#pragma unroll
        for (int nt = 0; nt < 8; ++nt) {
            const int col = nt * 8 + 2 * t;
            *(uint32_t*)&gOh[orow0 + col] = pack_f2h(o[nt][0] * inv0, o[nt][1] * inv0);
            *(uint32_t*)&gOh[orow1 + col] = pack_f2h(o[nt][2] * inv1, o[nt][3] * inv1);
        }
    } else {
        float* Op = gOp[z];
#pragma unroll
        for (int nt = 0; nt < 8; ++nt) {
            const int col = nt * 8 + 2 * t;
            *(float2*)&Op[orow0 + col] = make_float2(o[nt][0], o[nt][1]);
            *(float2*)&Op[orow1 + col] = make_float2(o[nt][2], o[nt][3]);
        }
        if (t == 0) {
            gMp[z][rg0 * NH + h] = m0;
            gLp[z][rg0 * NH + h] = l0;
            gMp[z][(rg0 + 8) * NH + h] = m1;
            gLp[z][(rg0 + 8) * NH + h] = l1;
        }
    }
}

// ---------------------------------------------------------------------------
// Merge split partials: O = (O0*2^(m0-M) + O1*2^(m1-M)) / (l0*2^(m0-M)+...)
// One 16-thread group per (row, head); 4 dims per thread.
// ---------------------------------------------------------------------------
__global__ __launch_bounds__(256) void attn_combine() {
    const int gid = blockIdx.x * 256 + threadIdx.x;  // 4096*256 = 1M threads
    const int p = gid >> 4;        // (row, head) pair
    const int dq = gid & 15;
    const int row = p >> 4;
    const int h = p & 15;
    const int it = (row & (SEQ - 1)) >> 7;
    const float slope = exp2f(-0.5f * (float)(h + 1));
    const int Jt_cap = min(32, (int)(100.f / slope) / 64 + 1);
    const int JtF = min(2 * it + 2, Jt_cap);
    if (JtF < SPLIT_MIN) return;   // row written directly by attn

    const int mi = row * NH + h;
    const float m0 = gMp[0][mi], m1 = gMp[1][mi];
    const float l0 = gLp[0][mi], l1 = gLp[1][mi];
    const float M = fmaxf(m0, m1);
    const float c0 = exp2f(m0 - M), c1 = exp2f(m1 - M);
    const float inv = 1.f / (l0 * c0 + l1 * c1);

    const size_t base = (size_t)row * DIM + h * HDIM + dq * 4;
    float4 a = *(const float4*)&gOp[0][base];
    float4 b = *(const float4*)&gOp[1][base];
    float f0 = (a.x * c0 + b.x * c1) * inv;
    float f1 = (a.y * c0 + b.y * c1) * inv;
    float f2 = (a.z * c0 + b.z * c1) * inv;
    float f3 = (a.w * c0 + b.w * c1) * inv;
    *(uint2*)&gOh[base] = make_uint2(pack_f2h(f0, f1), pack_f2h(f2, f3));
}

// ---------------------------------------------------------------------------
extern "C" void kernel_launch(void* const* d_in, const int* in_sizes, int n_in,
                              void* d_out, int out_size) {
    const float* X  = (const float*)d_in[0];
    const float* Wq = (const float*)d_in[1];
    const float* bq = (const float*)d_in[2];
    const float* Wk = (const float*)d_in[3];
    const float* bk = (const float*)d_in[4];
    const float* Wv = (const float*)d_in[5];
    const float* Wo = (const float*)d_in[6];
    const float* bo = (const float*)d_in[7];
    float* out = (float*)d_out;

    cudaFuncSetAttribute(qkv_mma, cudaFuncAttributeMaxDynamicSharedMemorySize, GEMM_SMEM);
    cudaFuncSetAttribute(out_mma, cudaFuncAttributeMaxDynamicSharedMemorySize, GEMM_SMEM);
    cudaFuncSetAttribute(attn_mma, cudaFuncAttributeMaxDynamicSharedMemorySize, ATTN_SMEM);

    convert_inputs<<<2048, 256>>>(X, Wq, Wk, Wv, Wo);
    qkv_mma<<<dim3(DIM / 128, MROWS / 128, 3), 256, GEMM_SMEM>>>(bq, bk);
    attn_mma<<<dim3(32, BQ * NH), 256, ATTN_SMEM>>>();
    attn_combine<<<4096, 256>>>();
    out_mma<<<dim3(DIM / 128, MROWS / 128, 1), 256, GEMM_SMEM>>>(bo, out);
}

// round 17
// speedup vs baseline: 1.0270x; 1.0270x over previous
#include <cuda_runtime.h>
#include <cuda_fp16.h>
#include <math.h>
#include <stdint.h>

// Problem constants
#define BQ   2
#define SEQ  2048
#define DIM  1024
#define NH   16
#define HDIM 64
#define MROWS (BQ * SEQ)   // 4096
#define LOG2E 1.4426950408889634f

// Scratch: everything single fp16 (calibrated error budget allows it).
__device__ __half gXh[MROWS * DIM];
__device__ __half gWh[4 * DIM * DIM];
__device__ __half gQh[MROWS * DIM];
__device__ __half gKh[MROWS * DIM];
__device__ __half gVh[MROWS * DIM];
__device__ __half gOh[MROWS * DIM];
// split-KV partials (unnormalized O + per-row max/sum in log2 domain)
__device__ float gOp[3][(size_t)MROWS * DIM];
__device__ float gMp[3][MROWS * NH];
__device__ float gLp[3][MROWS * NH];

__device__ __forceinline__ int nck_of(int JtF) {
    return (JtF >= 24) ? 3 : (JtF >= 12 ? 2 : 1);
}

// ---------------------------------------------------------------------------
// Helpers
// ---------------------------------------------------------------------------
__device__ __forceinline__ uint32_t smem_u32(const void* p) {
    uint32_t a;
    asm("{ .reg .u64 t; cvta.to.shared.u64 t, %1; cvt.u32.u64 %0, t; }"
        : "=r"(a) : "l"(p));
    return a;
}
__device__ __forceinline__ void cp16(uint32_t dst, const void* src) {
    asm volatile("cp.async.cg.shared.global [%0], [%1], 16;"
                 :: "r"(dst), "l"(__cvta_generic_to_global(src)));
}
__device__ __forceinline__ void cp_commit() {
    asm volatile("cp.async.commit_group;" ::: "memory");
}
__device__ __forceinline__ void ldsm4(uint32_t* r, uint32_t addr) {
    asm volatile("ldmatrix.sync.aligned.m8n8.x4.shared.b16 {%0,%1,%2,%3}, [%4];"
                 : "=r"(r[0]), "=r"(r[1]), "=r"(r[2]), "=r"(r[3]) : "r"(addr));
}
__device__ __forceinline__ void ldsm4t(uint32_t* r, uint32_t addr) {
    asm volatile("ldmatrix.sync.aligned.m8n8.x4.trans.shared.b16 {%0,%1,%2,%3}, [%4];"
                 : "=r"(r[0]), "=r"(r[1]), "=r"(r[2]), "=r"(r[3]) : "r"(addr));
}
__device__ __forceinline__ void mma16816(float* c, const uint32_t* a, const uint32_t* b) {
    asm volatile(
        "mma.sync.aligned.m16n8k16.row.col.f32.f16.f16.f32 "
        "{%0,%1,%2,%3}, {%4,%5,%6,%7}, {%8,%9}, {%0,%1,%2,%3};"
        : "+f"(c[0]), "+f"(c[1]), "+f"(c[2]), "+f"(c[3])
        : "r"(a[0]), "r"(a[1]), "r"(a[2]), "r"(a[3]), "r"(b[0]), "r"(b[1]));
}
__device__ __forceinline__ uint32_t pack_f2h(float a, float b) {
    __half2 t = __halves2half2(__float2half_rn(a), __float2half_rn(b));
    return *(uint32_t*)&t;
}

// ---------------------------------------------------------------------------
// Convert fp32 inputs -> single fp16 (X and the 4 weight matrices)
// ---------------------------------------------------------------------------
__global__ __launch_bounds__(256) void convert_inputs(
    const float* __restrict__ X, const float* __restrict__ Wq,
    const float* __restrict__ Wk, const float* __restrict__ Wv,
    const float* __restrict__ Wo) {
    const int XQ = MROWS * DIM / 4;
    const int WQ = DIM * DIM / 4;
    const int total4 = XQ + 4 * WQ;
    for (int i = blockIdx.x * blockDim.x + threadIdx.x; i < total4;
         i += gridDim.x * blockDim.x) {
        const float* src;
        __half* dh;
        if (i < XQ) {
            int e = i * 4;
            src = X + e; dh = gXh + e;
        } else {
            int t = i - XQ;
            int w = t / WQ;
            int off = (t - w * WQ) * 4;
            src = (w == 0) ? Wq + off : (w == 1) ? Wk + off
                  : (w == 2) ? Wv + off : Wo + off;
            dh = gWh + (size_t)w * DIM * DIM + off;
        }
        float4 v = *(const float4*)src;
        ((uint32_t*)dh)[0] = pack_f2h(v.x, v.y);
        ((uint32_t*)dh)[1] = pack_f2h(v.z, v.w);
    }
}

// ---------------------------------------------------------------------------
// Single-term fp16 GEMM (R15 config, unchanged): 128x128 CTA tile, K-step 64,
// 8 warps (64x32 tiles), 2-stage cp.async, 2 CTAs/SM.
// ---------------------------------------------------------------------------
#define STAGE_BYTES 32768
#define SM_BH 16384
#define GEMM_SMEM (2 * STAGE_BYTES)

__device__ __forceinline__ void gemm_fill(uint32_t sbuf,
                                          const __half* __restrict__ A,
                                          const __half* __restrict__ B,
                                          int row0, int col0, int kt, int tid) {
#pragma unroll
    for (int i = 0; i < 4; ++i) {
        int lin = tid + i * 256;
        int m = lin >> 3, c = lin & 7;
        cp16(sbuf + m * 128 + ((c ^ (m & 7)) << 4),
             A + (size_t)(row0 + m) * DIM + kt + c * 8);
    }
#pragma unroll
    for (int i = 0; i < 4; ++i) {
        int lin = tid + i * 256;
        int k = lin >> 4, c = lin & 15;
        cp16(sbuf + SM_BH + k * 256 + ((c >> 3) << 7) +
                 (((c & 7) ^ (k & 7)) << 4),
             B + (size_t)(kt + k) * DIM + col0 + c * 8);
    }
}

template <int OMODE>
__device__ __forceinline__ void mma_gemm_body(
    const __half* __restrict__ Ag, const __half* __restrict__ Bg,
    const float* __restrict__ bias, float* __restrict__ Yf,
    __half* __restrict__ Yh) {
    extern __shared__ __align__(1024) char smem[];
    const uint32_t sb = smem_u32(smem);
    const int tid = threadIdx.x;
    const int row0 = blockIdx.y * 128, col0 = blockIdx.x * 128;
    const int lane = tid & 31, wid = tid >> 5;
    const int wm = wid & 1, wn = wid >> 1;
    const int q = lane >> 3, r = lane & 7;
    const int arow = (q & 1) * 8 + r;
    const int aq = q >> 1;

    float acc[4][4][4];
#pragma unroll
    for (int mt = 0; mt < 4; ++mt)
#pragma unroll
        for (int nt = 0; nt < 4; ++nt)
#pragma unroll
            for (int e = 0; e < 4; ++e) acc[mt][nt][e] = 0.f;

    gemm_fill(sb, Ag, Bg, row0, col0, 0, tid);
    cp_commit();

    for (int s = 0; s < 16; ++s) {
        const int buf = s & 1;
        if (s + 1 < 16) {
            gemm_fill(sb + (buf ^ 1) * STAGE_BYTES, Ag, Bg, row0, col0,
                      (s + 1) * 64, tid);
            cp_commit();
            asm volatile("cp.async.wait_group 1;" ::: "memory");
        } else {
            asm volatile("cp.async.wait_group 0;" ::: "memory");
        }
        __syncthreads();

        const uint32_t sA = sb + buf * STAGE_BYTES;
        const uint32_t sBh = sA + SM_BH;

#pragma unroll
        for (int k16 = 0; k16 < 4; ++k16) {
            uint32_t bh[8];
            {
                const int krow = k16 * 16 + (q & 1) * 8 + r;
#pragma unroll
                for (int g2 = 0; g2 < 2; ++g2) {
                    int cg = wn * 4 + g2 * 2 + (q >> 1);
                    uint32_t baddr = krow * 256 + ((cg >> 3) << 7) +
                                     (((cg & 7) ^ (krow & 7)) << 4);
                    ldsm4t(&bh[g2 * 4], sBh + baddr);
                }
            }
            uint32_t ah[4][4];
#pragma unroll
            for (int mt = 0; mt < 4; ++mt) {
                int row = wm * 64 + mt * 16 + arow;
                int c1 = k16 * 2 + aq;
                ldsm4(ah[mt], sA + row * 128 + ((c1 ^ r) << 4));
            }
#pragma unroll
            for (int mt = 0; mt < 4; ++mt)
#pragma unroll
                for (int nt = 0; nt < 4; ++nt)
                    mma16816(acc[mt][nt], ah[mt], &bh[(nt >> 1) * 4 + (nt & 1) * 2]);
        }
        __syncthreads();
    }

    const int cg = lane >> 2, ct = lane & 3;
#pragma unroll
    for (int mt = 0; mt < 4; ++mt) {
        int r0 = row0 + wm * 64 + mt * 16 + cg;
#pragma unroll
        for (int nt = 0; nt < 4; ++nt) {
            int col = col0 + wn * 32 + nt * 8 + ct * 2;
            float b0 = bias ? bias[col] : 0.f;
            float b1 = bias ? bias[col + 1] : 0.f;
            float v00 = acc[mt][nt][0] + b0, v01 = acc[mt][nt][1] + b1;
            float v10 = acc[mt][nt][2] + b0, v11 = acc[mt][nt][3] + b1;
            if (OMODE == 0) {
                *(float2*)(Yf + (size_t)r0 * DIM + col) = make_float2(v00, v01);
                *(float2*)(Yf + (size_t)(r0 + 8) * DIM + col) = make_float2(v10, v11);
            } else {
                *(uint32_t*)&Yh[(size_t)r0 * DIM + col] = pack_f2h(v00, v01);
                *(uint32_t*)&Yh[(size_t)(r0 + 8) * DIM + col] = pack_f2h(v10, v11);
            }
        }
    }
}

__global__ __launch_bounds__(256, 2) void qkv_mma(const float* __restrict__ bq,
                                                  const float* __restrict__ bk) {
    const int z = blockIdx.z;
    const __half* B = gWh + (size_t)z * DIM * DIM;
    const float* bias = (z == 0) ? bq : (z == 1) ? bk : nullptr;
    __half* Yh = (z == 0) ? gQh : (z == 1) ? gKh : gVh;
    mma_gemm_body<3>(gXh, B, bias, nullptr, Yh);
}

__global__ __launch_bounds__(256, 2) void out_mma(const float* __restrict__ bo,
                                                  float* __restrict__ out) {
    mma_gemm_body<0>(gOh, gWh + (size_t)3 * DIM * DIM, bo, out, nullptr);
}

// ---------------------------------------------------------------------------
// Flash attention with up-to-3-way split-KV. j-tile = 64, 3-stage pipeline,
// 2 CTAs/SM, log2-domain softmax. CTAs with wide ALiBi/causal windows are
// split along j into nck chunks (nck = 3 if Jt>=24, 2 if Jt>=12, else 1);
// each chunk emits unnormalized partials merged by attn_combine.
// grid = (48, 32): blockIdx.x = (15-it)*3 + z, heavy i-tiles first.
// ---------------------------------------------------------------------------
#define A_ST0 16384
#define A_STAGE 16384
#define ATTN_SMEM (16384 + 3 * 16384)

__device__ __forceinline__ void attn_fill_kv(uint32_t st, int krow_base,
                                             int hcol, int tid) {
#pragma unroll
    for (int i = 0; i < 4; ++i) {
        int lin = tid + i * 256;
        int tz = lin >> 9;            // 0=Kh 1=Vh
        int rem = lin & 511;
        int m = rem >> 3, c = rem & 7;
        const __half* src = (tz ? gVh : gKh) +
                            (size_t)(krow_base + m) * DIM + hcol + c * 8;
        cp16(st + tz * 8192 + m * 128 + ((c ^ (m & 7)) << 4), src);
    }
}

__global__ __launch_bounds__(256, 2) void attn_mma() {
    extern __shared__ __align__(1024) char smem[];
    const uint32_t sb = smem_u32(smem);
    const int tid = threadIdx.x;
    const int lane = tid & 31, w = tid >> 5;
    const int q = lane >> 3, r = lane & 7;
    const int g = lane >> 2, t = lane & 3;
    const int itz = blockIdx.x;
    const int it = 15 - itz / 3;             // heavy i-tiles first
    const int z = itz % 3;
    const int y = blockIdx.y;
    const int b = y & 1;
    const int h = 15 - (y >> 1);             // heavy heads first
    const int i0 = it * 128;
    const float slope = exp2f(-0.5f * (float)(h + 1));
    const float qsc = 0.125f * LOG2E;
    const float sl2 = slope * LOG2E;
    const int qrow_base = b * SEQ + i0;
    const int hcol = h * HDIM;
    const int kbase = b * SEQ;

    // window (bit-exact) + split decision
    const int Jt_cap = min(32, (int)(100.f / slope) / 64 + 1);
    const int JtF = min(2 * it + 2, Jt_cap);        // >= 2
    const int nck = nck_of(JtF);
    if (z >= nck) return;
    const int jlo = z * JtF / nck;
    const int jhi = (z + 1) * JtF / nck;            // span >= 2 always

    // ---- fill Q (16KB) + K/V stages jlo, jlo+1 ----
#pragma unroll
    for (int i = 0; i < 4; ++i) {
        int lin = tid + i * 256;
        int m = lin >> 3, c = lin & 7;
        cp16(sb + m * 128 + ((c ^ (m & 7)) << 4),
             gQh + (size_t)(qrow_base + m) * DIM + hcol + c * 8);
    }
    attn_fill_kv(sb + A_ST0, kbase + jlo * 64, hcol, tid);
    cp_commit();
    attn_fill_kv(sb + A_ST0 + A_STAGE, kbase + (jlo + 1) * 64, hcol, tid);
    cp_commit();

    float o[8][4];
#pragma unroll
    for (int nt = 0; nt < 8; ++nt)
#pragma unroll
        for (int e = 0; e < 4; ++e) o[nt][e] = 0.f;
    float m0 = -1e30f, m1 = -1e30f, l0 = 0.f, l1 = 0.f;
    uint32_t qh[4][4];

    const int rowlast = i0 + w * 16 + 15;
    for (int jt = jlo; jt < jhi; ++jt) {
        const int buf = (jt - jlo) % 3;
        if (jt + 2 < jhi) {
            attn_fill_kv(sb + A_ST0 + ((jt - jlo + 2) % 3) * A_STAGE,
                         kbase + (jt + 2) * 64, hcol, tid);
            cp_commit();
            asm volatile("cp.async.wait_group 2;" ::: "memory");
        } else if (jt + 1 < jhi) {
            asm volatile("cp.async.wait_group 1;" ::: "memory");
        } else {
            asm volatile("cp.async.wait_group 0;" ::: "memory");
        }
        __syncthreads();

        if (jt == jlo) {  // hoist Q fragments
#pragma unroll
            for (int k16 = 0; k16 < 4; ++k16) {
                int row = w * 16 + (q & 1) * 8 + r;
                int c = k16 * 2 + (q >> 1);
                ldsm4(qh[k16], sb + row * 128 + ((c ^ r) << 4));
            }
        }

        const uint32_t sk = sb + A_ST0 + buf * A_STAGE;
        const uint32_t sv = sk + 8192;
        const int j0 = jt * 64;
        const bool maskzone = (j0 + 63) > (i0 + w * 16);

        // ---- S = Q K^T over 64 keys ----
        float s[8][4];
#pragma unroll
        for (int nt16 = 0; nt16 < 4; ++nt16) {
#pragma unroll
            for (int e = 0; e < 4; ++e) {
                s[2 * nt16][e] = 0.f;
                s[2 * nt16 + 1][e] = 0.f;
            }
            if (j0 + nt16 * 16 > rowlast) continue;
            const int row = nt16 * 16 + (q >> 1) * 8 + r;
#pragma unroll
            for (int k16 = 0; k16 < 4; ++k16) {
                const int c = k16 * 2 + (q & 1);
                uint32_t kh[4];
                ldsm4(kh, sk + row * 128 + ((c ^ r) << 4));
                mma16816(s[2 * nt16], qh[k16], kh);
                mma16816(s[2 * nt16 + 1], qh[k16], kh + 2);
            }
        }

        // ---- online softmax (log2 domain) ----
        const int rowg0 = i0 + w * 16 + g;
        const int rowg1 = rowg0 + 8;
        float mx0 = -1e30f, mx1 = -1e30f;
#pragma unroll
        for (int nt = 0; nt < 8; ++nt) {
            const int jc = j0 + nt * 8 + 2 * t;
            const float c0 = (float)jc;
            s[nt][0] = s[nt][0] * qsc - sl2 * c0;
            s[nt][1] = s[nt][1] * qsc - sl2 * (c0 + 1.f);
            s[nt][2] = s[nt][2] * qsc - sl2 * c0;
            s[nt][3] = s[nt][3] * qsc - sl2 * (c0 + 1.f);
            if (maskzone) {
                if (jc > rowg0) s[nt][0] = -1e30f;
                if (jc + 1 > rowg0) s[nt][1] = -1e30f;
                if (jc > rowg1) s[nt][2] = -1e30f;
                if (jc + 1 > rowg1) s[nt][3] = -1e30f;
            }
            mx0 = fmaxf(mx0, fmaxf(s[nt][0], s[nt][1]));
            mx1 = fmaxf(mx1, fmaxf(s[nt][2], s[nt][3]));
        }
        mx0 = fmaxf(mx0, __shfl_xor_sync(0xffffffffu, mx0, 1, 4));
        mx0 = fmaxf(mx0, __shfl_xor_sync(0xffffffffu, mx0, 2, 4));
        mx1 = fmaxf(mx1, __shfl_xor_sync(0xffffffffu, mx1, 1, 4));
        mx1 = fmaxf(mx1, __shfl_xor_sync(0xffffffffu, mx1, 2, 4));
        const float mn0 = fmaxf(m0, mx0), mn1 = fmaxf(m1, mx1);
        const float cr0 = exp2f(m0 - mn0), cr1 = exp2f(m1 - mn1);
        m0 = mn0;
        m1 = mn1;
        float sum0 = 0.f, sum1 = 0.f;
#pragma unroll
        for (int nt = 0; nt < 8; ++nt) {
            s[nt][0] = exp2f(s[nt][0] - mn0);
            s[nt][1] = exp2f(s[nt][1] - mn0);
            s[nt][2] = exp2f(s[nt][2] - mn1);
            s[nt][3] = exp2f(s[nt][3] - mn1);
            sum0 += s[nt][0] + s[nt][1];
            sum1 += s[nt][2] + s[nt][3];
        }
        sum0 += __shfl_xor_sync(0xffffffffu, sum0, 1, 4);
        sum0 += __shfl_xor_sync(0xffffffffu, sum0, 2, 4);
        sum1 += __shfl_xor_sync(0xffffffffu, sum1, 1, 4);
        sum1 += __shfl_xor_sync(0xffffffffu, sum1, 2, 4);
        l0 = l0 * cr0 + sum0;
        l1 = l1 * cr1 + sum1;
#pragma unroll
        for (int nt = 0; nt < 8; ++nt) {
            o[nt][0] *= cr0;
            o[nt][1] *= cr0;
            o[nt][2] *= cr1;
            o[nt][3] *= cr1;
        }

        // ---- O += P V over 64 keys ----
#pragma unroll
        for (int k16 = 0; k16 < 4; ++k16) {
            if (j0 + k16 * 16 > rowlast) continue;
            uint32_t ph[4];
            ph[0] = pack_f2h(s[2 * k16][0], s[2 * k16][1]);
            ph[1] = pack_f2h(s[2 * k16][2], s[2 * k16][3]);
            ph[2] = pack_f2h(s[2 * k16 + 1][0], s[2 * k16 + 1][1]);
            ph[3] = pack_f2h(s[2 * k16 + 1][2], s[2 * k16 + 1][3]);
            const int row = k16 * 16 + (q & 1) * 8 + r;
#pragma unroll
            for (int cgp = 0; cgp < 4; ++cgp) {
                const int c = cgp * 2 + (q >> 1);
                uint32_t vh[4];
                ldsm4t(vh, sv + row * 128 + ((c ^ r) << 4));
                mma16816(o[cgp * 2], ph, vh);
                mma16816(o[cgp * 2 + 1], ph, vh + 2);
            }
        }
        __syncthreads();
    }

    // ---- epilogue ----
    const int rg0 = qrow_base + w * 16 + g;
    const size_t orow0 = (size_t)rg0 * DIM + hcol;
    const size_t orow1 = orow0 + (size_t)8 * DIM;
    if (nck == 1) {
        const float inv0 = 1.f / l0, inv1 = 1.f / l1;
#pragma unroll
        for (int nt = 0; nt < 8; ++nt) {
            const int col = nt * 8 + 2 * t;
            *(uint32_t*)&gOh[orow0 + col] = pack_f2h(o[nt][0] * inv0, o[nt][1] * inv0);
            *(uint32_t*)&gOh[orow1 + col] = pack_f2h(o[nt][2] * inv1, o[nt][3] * inv1);
        }
    } else {
        float* Op = gOp[z];
#pragma unroll
        for (int nt = 0; nt < 8; ++nt) {
            const int col = nt * 8 + 2 * t;
            *(float2*)&Op[orow0 + col] = make_float2(o[nt][0], o[nt][1]);
            *(float2*)&Op[orow1 + col] = make_float2(o[nt][2], o[nt][3]);
        }
        if (t == 0) {
            gMp[z][rg0 * NH + h] = m0;
            gLp[z][rg0 * NH + h] = l0;
            gMp[z][(rg0 + 8) * NH + h] = m1;
            gLp[z][(rg0 + 8) * NH + h] = l1;
        }
    }
}

// ---------------------------------------------------------------------------
// Merge up to 3 split partials (log-sum-exp in log2 domain).
// One 16-thread group per (row, head); 4 dims per thread.
// ---------------------------------------------------------------------------
__global__ __launch_bounds__(256) void attn_combine() {
    const int gid = blockIdx.x * 256 + threadIdx.x;
    const int p = gid >> 4;
    const int dq = gid & 15;
    const int row = p >> 4;
    const int h = p & 15;
    const int it = (row & (SEQ - 1)) >> 7;
    const float slope = exp2f(-0.5f * (float)(h + 1));
    const int Jt_cap = min(32, (int)(100.f / slope) / 64 + 1);
    const int JtF = min(2 * it + 2, Jt_cap);
    const int nck = nck_of(JtF);
    if (nck == 1) return;   // row written directly by attn

    const int mi = row * NH + h;
    const float m0 = gMp[0][mi], m1 = gMp[1][mi];
    const float m2 = (nck == 3) ? gMp[2][mi] : -1e30f;
    const float l0 = gLp[0][mi], l1 = gLp[1][mi];
    const float l2 = (nck == 3) ? gLp[2][mi] : 0.f;
    const float M = fmaxf(fmaxf(m0, m1), m2);
    const float c0 = exp2f(m0 - M), c1 = exp2f(m1 - M);
    const float c2 = (nck == 3) ? exp2f(m2 - M) : 0.f;
    const float inv = 1.f / (l0 * c0 + l1 * c1 + l2 * c2);

    const size_t base = (size_t)row * DIM + h * HDIM + dq * 4;
    float4 a = *(const float4*)&gOp[0][base];
    float4 b = *(const float4*)&gOp[1][base];
    float f0 = a.x * c0 + b.x * c1;
    float f1 = a.y * c0 + b.y * c1;
    float f2 = a.z * c0 + b.z * c1;
    float f3 = a.w * c0 + b.w * c1;
    if (nck == 3) {
        float4 c = *(const float4*)&gOp[2][base];
        f0 += c.x * c2;
        f1 += c.y * c2;
        f2 += c.z * c2;
        f3 += c.w * c2;
    }
    f0 *= inv; f1 *= inv; f2 *= inv; f3 *= inv;
    *(uint2*)&gOh[base] = make_uint2(pack_f2h(f0, f1), pack_f2h(f2, f3));
}

// ---------------------------------------------------------------------------
extern "C" void kernel_launch(void* const* d_in, const int* in_sizes, int n_in,
                              void* d_out, int out_size) {
    const float* X  = (const float*)d_in[0];
    const float* Wq = (const float*)d_in[1];
    const float* bq = (const float*)d_in[2];
    const float* Wk = (const float*)d_in[3];
    const float* bk = (const float*)d_in[4];
    const float* Wv = (const float*)d_in[5];
    const float* Wo = (const float*)d_in[6];
    const float* bo = (const float*)d_in[7];
    float* out = (float*)d_out;

    cudaFuncSetAttribute(qkv_mma, cudaFuncAttributeMaxDynamicSharedMemorySize, GEMM_SMEM);
    cudaFuncSetAttribute(out_mma, cudaFuncAttributeMaxDynamicSharedMemorySize, GEMM_SMEM);
    cudaFuncSetAttribute(attn_mma, cudaFuncAttributeMaxDynamicSharedMemorySize, ATTN_SMEM);

    convert_inputs<<<2048, 256>>>(X, Wq, Wk, Wv, Wo);
    qkv_mma<<<dim3(DIM / 128, MROWS / 128, 3), 256, GEMM_SMEM>>>(bq, bk);
    attn_mma<<<dim3(48, BQ * NH), 256, ATTN_SMEM>>>();
    attn_combine<<<4096, 256>>>();
    out_mma<<<dim3(DIM / 128, MROWS / 128, 1), 256, GEMM_SMEM>>>(bo, out);
}